// round 2
// baseline (speedup 1.0000x reference)
#include <cuda_runtime.h>

#define B_   256
#define R_   1152
#define C_   10
#define IC_  8
#define OC_  16
#define RT_  16
#define CHUNKS_ (R_/RT_)   /* 72 */

// Scratch (static device memory — no allocations).
__device__ __align__(16) float g_Vsum[B_*C_*OC_];                 // running sum of v_j
__device__ __align__(16) float g_scratch[CHUNKS_*B_*C_*OC_];      // per-r-chunk partial s

__global__ void init_kernel() {
    int i = blockIdx.x * blockDim.x + threadIdx.x;
    if (i < B_*C_*OC_) g_Vsum[i] = 0.0f;
}

// One fused routing pass. Grid: (CHUNKS_, 2), block 512.
// Thread -> (b = by*128 + tid/4, o-quarter = tid&3). s[10][4], u[10][4] in regs.
template<bool FIRST>
__global__ __launch_bounds__(512, 1)
void pass_kernel(const float* __restrict__ x, const float* __restrict__ w) {
    extern __shared__ float4 Ws[];            // [RT_][C_][IC_][4] float4 = 80 KB
    const int tid   = threadIdx.x;
    const int chunk = blockIdx.x;
    const int r0    = chunk * RT_;
    const int oq    = tid & 3;                // which 4-wide quarter of OC
    const int b     = blockIdx.y * 128 + (tid >> 2);

    // Cooperative load of the W tile for RT_ routes (coalesced, float4).
    const float4* wsrc = reinterpret_cast<const float4*>(w) + (size_t)r0 * (C_*IC_*4);
    #pragma unroll
    for (int k = 0; k < (RT_*C_*IC_*4)/512; ++k) Ws[k*512 + tid] = wsrc[k*512 + tid];
    __syncthreads();

    float s[C_][4];
    #pragma unroll
    for (int c = 0; c < C_; ++c)
        #pragma unroll
        for (int j = 0; j < 4; ++j) s[c][j] = 0.0f;

    const float* xrow = x + ((size_t)b * R_ + r0) * IC_;
    const float* vsum = g_Vsum + b * (C_*OC_) + oq * 4;

    #pragma unroll 1
    for (int r = 0; r < RT_; ++r) {
        float4 xa = *reinterpret_cast<const float4*>(xrow + r*IC_);
        float4 xb = *reinterpret_cast<const float4*>(xrow + r*IC_ + 4);
        float xi[8] = {xa.x, xa.y, xa.z, xa.w, xb.x, xb.y, xb.z, xb.w};

        const float4* wr = &Ws[(size_t)r * (C_*IC_*4) + oq];

        if (FIRST) {
            // uniform coupling: accumulate u straight into s (no u array)
            #pragma unroll
            for (int c = 0; c < C_; ++c) {
                #pragma unroll
                for (int i = 0; i < IC_; ++i) {
                    float4 wq = wr[(c*IC_ + i)*4];     // smem, 64B/warp broadcast
                    s[c][0] += xi[i]*wq.x; s[c][1] += xi[i]*wq.y;
                    s[c][2] += xi[i]*wq.z; s[c][3] += xi[i]*wq.w;
                }
            }
        } else {
            float u[C_][4];
            float t[C_];
            #pragma unroll
            for (int c = 0; c < C_; ++c) {
                float a0=0.f, a1=0.f, a2=0.f, a3=0.f;
                #pragma unroll
                for (int i = 0; i < IC_; ++i) {
                    float4 wq = wr[(c*IC_ + i)*4];
                    a0 += xi[i]*wq.x; a1 += xi[i]*wq.y;
                    a2 += xi[i]*wq.z; a3 += xi[i]*wq.w;
                }
                u[c][0]=a0; u[c][1]=a1; u[c][2]=a2; u[c][3]=a3;
                float4 vq = *reinterpret_cast<const float4*>(vsum + c*OC_);  // L1-hit
                t[c] = a0*vq.x + a1*vq.y + a2*vq.z + a3*vq.w;
            }

            // complete t over the 4 o-quarter lanes (same b)
            #pragma unroll
            for (int c = 0; c < C_; ++c) {
                t[c] += __shfl_xor_sync(0xffffffffu, t[c], 1);
                t[c] += __shfl_xor_sync(0xffffffffu, t[c], 2);
            }
            float m = t[0];
            #pragma unroll
            for (int c = 1; c < C_; ++c) m = fmaxf(m, t[c]);
            float sum = 0.0f;
            float coef[C_];
            #pragma unroll
            for (int c = 0; c < C_; ++c) { coef[c] = __expf(t[c] - m); sum += coef[c]; }
            float inv = __fdividef(1.0f, sum);

            #pragma unroll
            for (int c = 0; c < C_; ++c) {
                float cc = coef[c] * inv;
                s[c][0] += cc*u[c][0]; s[c][1] += cc*u[c][1];
                s[c][2] += cc*u[c][2]; s[c][3] += cc*u[c][3];
            }
        }
    }

    // Write per-chunk partial s (no atomics; reduced in squash kernel).
    float* dst = g_scratch + ((size_t)chunk * B_ + b) * (C_*OC_) + oq * 4;
    const float fscale = FIRST ? 0.1f : 1.0f;
    #pragma unroll
    for (int c = 0; c < C_; ++c) {
        float4 p = make_float4(s[c][0]*fscale, s[c][1]*fscale,
                               s[c][2]*fscale, s[c][3]*fscale);
        *reinterpret_cast<float4*>(dst + c*OC_) = p;
    }
}

// Reduce 72 partials, squash, update Vsum (or emit final output).
// Grid: 160 x 256 = 40960 threads, one per (b,c,o). 16-lane groups share (b,c).
template<bool LAST>
__global__ void squash_kernel(float* __restrict__ out) {
    int g = blockIdx.x * 256 + threadIdx.x;
    float s = 0.0f;
    #pragma unroll 8
    for (int k = 0; k < CHUNKS_; ++k) s += g_scratch[(size_t)k * (B_*C_*OC_) + g];
    float sq = s * s;
    #pragma unroll
    for (int m = 8; m >= 1; m >>= 1) sq += __shfl_xor_sync(0xffffffffu, sq, m);
    float n = sqrtf(sq);
    float v = (sq / (1.0f + sq)) * s / (n + 1e-8f);
    if (LAST) out[g] = v;
    else      g_Vsum[g] += v;
}

extern "C" void kernel_launch(void* const* d_in, const int* in_sizes, int n_in,
                              void* d_out, int out_size) {
    const float* x = (const float*)d_in[0];
    const float* w = (const float*)d_in[1];
    float* out = (float*)d_out;

    const size_t smem = (size_t)RT_ * C_ * IC_ * 4 * sizeof(float4);  // 81920 B
    cudaFuncSetAttribute(pass_kernel<true>,  cudaFuncAttributeMaxDynamicSharedMemorySize, (int)smem);
    cudaFuncSetAttribute(pass_kernel<false>, cudaFuncAttributeMaxDynamicSharedMemorySize, (int)smem);

    dim3 grid(CHUNKS_, 2);

    init_kernel<<<160, 256>>>();
    pass_kernel<true ><<<grid, 512, smem>>>(x, w);   // iter 1 (uniform coupling)
    squash_kernel<false><<<160, 256>>>(out);         // v1, Vsum = v1
    pass_kernel<false><<<grid, 512, smem>>>(x, w);   // iter 2
    squash_kernel<false><<<160, 256>>>(out);         // v2, Vsum = v1+v2
    pass_kernel<false><<<grid, 512, smem>>>(x, w);   // iter 3
    squash_kernel<true ><<<160, 256>>>(out);         // v3 -> output
}